// round 14
// baseline (speedup 1.0000x reference)
#include <cuda_runtime.h>
#include <cuda_fp16.h>
#include <math.h>
#include <cstdint>

static constexpr int T_   = 2048;
static constexpr int NH   = 32;
static constexpr int NPACK = 12544;
static constexpr int OFF_K = 2048;
static constexpr int OFF_V = 4096;
static constexpr int OFF_G = 8192;
static constexpr int OFF_A = 12288;
static constexpr int OFF_B2 = 12320;
static constexpr int OFF_END = 12352;

__device__ float  g_big [T_ * NPACK];
__device__ __half g_Wp  [2048 * NPACK];   // packed fp16 weights
__device__ __half g_hr  [T_ * 2048];      // fp16 h
__device__ __half g_WoR [4096 * 2048];    // fp16 Wo
__device__ __half g_og  [T_ * 4096];      // fp16 normed+gated
__device__ float  g_acts[T_ * 8192];      // only v region [4096,8192) used
__device__ float  g_egT [NH * T_];
__device__ float  g_btT [NH * T_];
__device__ float  g_qn  [T_ * 2048];      // l2-normed q, dk-permuted rows
__device__ float  g_kn  [T_ * 2048];
__device__ float  g_qkd [16 * T_];        // q_t . k_t        [hk][t]
__device__ float  g_kkx [16 * 1024];      // k_{2p+1} . k_2p  [hk][p]
__device__ float  g_qkx [16 * 1024];      // q_{2p+1} . k_2p  [hk][p]
__device__ float  g_o   [T_ * 4096];

__device__ __forceinline__ uint32_t smem_u32(const void* p) {
    uint32_t a;
    asm("{ .reg .u64 t; cvta.to.shared.u64 t, %1; cvt.u32.u64 %0, t; }" : "=r"(a) : "l"(p));
    return a;
}
__device__ __forceinline__ void cp16(uint32_t dst, const void* src) {
    asm volatile("cp.async.cg.shared.global [%0], [%1], 16;" :: "r"(dst), "l"(src));
}
#define CP_COMMIT() asm volatile("cp.async.commit_group;" ::: "memory")
#define CP_WAIT(n)  asm volatile("cp.async.wait_group %0;" :: "n"(n) : "memory")

__device__ __forceinline__ void ldsm_x4(uint32_t addr, uint32_t* r) {
    asm volatile("ldmatrix.sync.aligned.m8n8.x4.shared.b16 {%0,%1,%2,%3}, [%4];"
        : "=r"(r[0]), "=r"(r[1]), "=r"(r[2]), "=r"(r[3]) : "r"(addr));
}
__device__ __forceinline__ void ldsm_x2t(uint32_t addr, uint32_t* r) {
    asm volatile("ldmatrix.sync.aligned.m8n8.x2.trans.shared.b16 {%0,%1}, [%2];"
        : "=r"(r[0]), "=r"(r[1]) : "r"(addr));
}
__device__ __forceinline__ void mma_f16(float* c, const uint32_t* a, const uint32_t* b) {
    asm volatile("mma.sync.aligned.m16n8k16.row.col.f32.f16.f16.f32 "
        "{%0,%1,%2,%3}, {%4,%5,%6,%7}, {%8,%9}, {%0,%1,%2,%3};"
        : "+f"(c[0]), "+f"(c[1]), "+f"(c[2]), "+f"(c[3])
        : "r"(a[0]), "r"(a[1]), "r"(a[2]), "r"(a[3]), "r"(b[0]), "r"(b[1]));
}

// ---- packed f32x2 helpers (sm_100+ base ISA) ----
typedef unsigned long long u64;
__device__ __forceinline__ u64 f2b(float x) {
    u64 r; asm("mov.b64 %0, {%1, %1};" : "=l"(r) : "f"(x)); return r;
}
__device__ __forceinline__ float f2hadd(u64 v) {
    float a, b; asm("mov.b64 {%0, %1}, %2;" : "=f"(a), "=f"(b) : "l"(v)); return a + b;
}
__device__ __forceinline__ u64 f2fma(u64 a, u64 b, u64 c) {
    u64 d; asm("fma.rn.f32x2 %0, %1, %2, %3;" : "=l"(d) : "l"(a), "l"(b), "l"(c)); return d;
}
__device__ __forceinline__ u64 f2mul(u64 a, u64 b) {
    u64 d; asm("mul.rn.f32x2 %0, %1, %2;" : "=l"(d) : "l"(a), "l"(b)); return d;
}

// =====================================================================
// fp16 mma.sync GEMM (unchanged from R12, proven).
// =====================================================================
static constexpr uint32_t STAGE = 49152;
static constexpr uint32_t GEMM_SMEM = 4 * STAGE;   // 192KB

__global__ __launch_bounds__(512, 1) void mma_gemm(
    const __half* __restrict__ A, const __half* __restrict__ B, float* __restrict__ C,
    int K, int ldb, int ldc)
{
    extern __shared__ char smem[];
    const uint32_t sbase = smem_u32(smem);
    const int tid  = threadIdx.x;
    const int lane = tid & 31;
    const int w    = tid >> 5;
    const int wm   = w >> 2;
    const int wn   = w & 3;
    const int c4   = lane & 3;
    const int g    = lane >> 2;
    const int row0 = blockIdx.x * 256;
    const int col0 = blockIdx.y * 128;
    const int mA   = lane >> 3;
    const int iA   = lane & 7;

    float acc[4][4][4];
#pragma unroll
    for (int mi = 0; mi < 4; mi++)
#pragma unroll
        for (int ni = 0; ni < 4; ni++)
#pragma unroll
            for (int q = 0; q < 4; q++) acc[mi][ni][q] = 0.f;

    const int nt = K >> 6;

    auto issue = [&](int t, int st) {
        const int k0 = t << 6;
        const uint32_t sA = sbase + st * STAGE;
        const uint32_t sB = sA + 32768;
#pragma unroll
        for (int it = 0; it < 4; it++) {
            int idx = it * 512 + tid;
            int r = idx >> 3, f = idx & 7;
            cp16(sA + r * 128 + (((uint32_t)(f ^ (r & 7))) << 4),
                 A + (size_t)(row0 + r) * K + k0 + f * 8);
        }
#pragma unroll
        for (int it = 0; it < 2; it++) {
            int idx = it * 512 + tid;
            int k = idx >> 4, cn = idx & 15;
            cp16(sB + k * 256 + (((uint32_t)(cn ^ (k & 7))) << 4),
                 B + (size_t)(k0 + k) * ldb + col0 + cn * 8);
        }
    };

    auto compute = [&](int st) {
        const uint32_t sA = sbase + st * STAGE;
        const uint32_t sB = sA + 32768;
#pragma unroll
        for (int s = 0; s < 4; s++) {
            uint32_t af[4][4];
            uint32_t bf[4][2];
#pragma unroll
            for (int mi = 0; mi < 4; mi++) {
                int row = wm * 64 + mi * 16 + iA + ((mA & 1) << 3);
                int f = 2 * s + (mA >> 1);
                ldsm_x4(sA + row * 128 + (((uint32_t)(f ^ (row & 7))) << 4), af[mi]);
            }
#pragma unroll
            for (int ni = 0; ni < 4; ni++) {
                int cn = 4 * wn + ni;
                int k = 16 * s + ((mA & 1) << 3) + iA;
                ldsm_x2t(sB + k * 256 + (((uint32_t)(cn ^ (k & 7))) << 4), bf[ni]);
            }
#pragma unroll
            for (int mi = 0; mi < 4; mi++)
#pragma unroll
                for (int ni = 0; ni < 4; ni++)
                    mma_f16(acc[mi][ni], af[mi], bf[ni]);
        }
    };

    issue(0, 0); CP_COMMIT();
    issue(1, 1); CP_COMMIT();
    issue(2, 2); CP_COMMIT();
    int st = 0;
    for (int t = 0; t < nt; t++) {
        if (t + 3 < nt) {
            CP_WAIT(2);
            __syncthreads();
            issue(t + 3, (st + 3) & 3);
            CP_COMMIT();
        } else {
            CP_WAIT(0);
            __syncthreads();
        }
        compute(st);
        st = (st + 1) & 3;
    }

#pragma unroll
    for (int mi = 0; mi < 4; mi++) {
        const int r0 = row0 + wm * 64 + mi * 16 + g;
#pragma unroll
        for (int ni = 0; ni < 4; ni++) {
            const int cc = col0 + wn * 32 + ni * 8 + 2 * c4;
            *(float2*)(C + (size_t)r0 * ldc + cc) =
                make_float2(acc[mi][ni][0], acc[mi][ni][1]);
            *(float2*)(C + (size_t)(r0 + 8) * ldc + cc) =
                make_float2(acc[mi][ni][2], acc[mi][ni][3]);
        }
    }
}

// ================= weight pack (fp16) =================
__global__ void pack_w(const float* __restrict__ Wq, const float* __restrict__ Wk,
                       const float* __restrict__ Wv, const float* __restrict__ Wg,
                       const float* __restrict__ Wa, const float* __restrict__ Wb,
                       __half* __restrict__ P)
{
    int idx = blockIdx.x * 256 + threadIdx.x;
    int k = idx / 3136;
    int n = (idx - k * 3136) * 4;
    float4 v = make_float4(0.f, 0.f, 0.f, 0.f);
    if      (n < OFF_K)   v = *(const float4*)(Wq + (size_t)k * 2048 + n);
    else if (n < OFF_V)   v = *(const float4*)(Wk + (size_t)k * 2048 + n - OFF_K);
    else if (n < OFF_G)   v = *(const float4*)(Wv + (size_t)k * 4096 + n - OFF_V);
    else if (n < OFF_A)   v = *(const float4*)(Wg + (size_t)k * 4096 + n - OFF_G);
    else if (n < OFF_B2)  v = *(const float4*)(Wa + (size_t)k * 32 + n - OFF_A);
    else if (n < OFF_END) v = *(const float4*)(Wb + (size_t)k * 32 + n - OFF_B2);
    __half* p = P + (size_t)k * NPACK + n;
    *(__half2*)(p + 0) = __floats2half2_rn(v.x, v.y);
    *(__half2*)(p + 2) = __floats2half2_rn(v.z, v.w);
}

// float -> fp16 copy
__global__ void half_copy(const float* __restrict__ src, __half* __restrict__ dst)
{
    int i = (blockIdx.x * 256 + threadIdx.x) * 4;
    float4 v = *(const float4*)(src + i);
    *(__half2*)(dst + i + 0) = __floats2half2_rn(v.x, v.y);
    *(__half2*)(dst + i + 2) = __floats2half2_rn(v.z, v.w);
}

// =====================================================================
// Fused: v-conv+SiLU; q/k conv+SiLU+l2norm+permute; gate/beta (as R12).
// =====================================================================
__global__ void conv_norm(const float* __restrict__ big,
                          const float* __restrict__ cq, const float* __restrict__ ck,
                          const float* __restrict__ cv, const float* __restrict__ dtb,
                          const float* __restrict__ Alg, float* __restrict__ acts,
                          float* __restrict__ egT, float* __restrict__ btT,
                          float* __restrict__ qn, float* __restrict__ kn)
{
    int b = blockIdx.x;
    float4 z = make_float4(0.f, 0.f, 0.f, 0.f);
    if (b < 8192) {
        int gid = b * 256 + threadIdx.x;
        int t = gid >> 10;
        int c = (gid & 1023) << 2;
        const float* wp = cv + c * 4;
        float4 w0 = *(const float4*)(wp + 0), w1 = *(const float4*)(wp + 4);
        float4 w2 = *(const float4*)(wp + 8), w3 = *(const float4*)(wp + 12);
        const float* xp = big + (size_t)t * NPACK + 4096 + c;
        float4 x3 = *(const float4*)xp;
        float4 x2 = (t >= 1) ? *(const float4*)(xp - NPACK)     : z;
        float4 x1 = (t >= 2) ? *(const float4*)(xp - 2 * NPACK) : z;
        float4 x0 = (t >= 3) ? *(const float4*)(xp - 3 * NPACK) : z;
        float4 o;
        o.x = w0.x * x0.x + w0.y * x1.x + w0.z * x2.x + w0.w * x3.x;
        o.y = w1.x * x0.y + w1.y * x1.y + w1.z * x2.y + w1.w * x3.y;
        o.z = w2.x * x0.z + w2.y * x1.z + w2.z * x2.z + w2.w * x3.z;
        o.w = w3.x * x0.w + w3.y * x1.w + w3.z * x2.w + w3.w * x3.w;
        o.x = o.x / (1.f + expf(-o.x)); o.y = o.y / (1.f + expf(-o.y));
        o.z = o.z / (1.f + expf(-o.z)); o.w = o.w / (1.f + expf(-o.w));
        *(float4*)(acts + (size_t)t * 8192 + 4096 + c) = o;
    } else if (b < 16384) {
        int gw   = (b - 8192) * 8 + (threadIdx.x >> 5);
        int lane = threadIdx.x & 31;
        int t     = gw >> 5;
        int rest  = gw & 31;
        int which = rest & 1;
        int hh    = rest >> 1;
        int cl    = lane * 4;
        const float* wp = (which ? ck : cq) + (hh * 128 + cl) * 4;
        float4 w0 = *(const float4*)(wp + 0), w1 = *(const float4*)(wp + 4);
        float4 w2 = *(const float4*)(wp + 8), w3 = *(const float4*)(wp + 12);
        const float* xp = big + (size_t)t * NPACK + which * 2048 + hh * 128 + cl;
        float4 x3 = *(const float4*)xp;
        float4 x2 = (t >= 1) ? *(const float4*)(xp - NPACK)     : z;
        float4 x1 = (t >= 2) ? *(const float4*)(xp - 2 * NPACK) : z;
        float4 x0 = (t >= 3) ? *(const float4*)(xp - 3 * NPACK) : z;
        float v[4];
        v[0] = w0.x * x0.x + w0.y * x1.x + w0.z * x2.x + w0.w * x3.x;
        v[1] = w1.x * x0.y + w1.y * x1.y + w1.z * x2.y + w1.w * x3.y;
        v[2] = w2.x * x0.z + w2.y * x1.z + w2.z * x2.z + w2.w * x3.z;
        v[3] = w3.x * x0.w + w3.y * x1.w + w3.z * x2.w + w3.w * x3.w;
#pragma unroll
        for (int j = 0; j < 4; j++) v[j] = v[j] / (1.f + expf(-v[j]));
        float ss = v[0] * v[0] + v[1] * v[1] + v[2] * v[2] + v[3] * v[3];
#pragma unroll
        for (int off = 16; off; off >>= 1) ss += __shfl_xor_sync(0xffffffffu, ss, off);
        float s = rsqrtf(ss + 1e-6f);
        if (which == 0) s *= 0.08838834764831845f;
        float* dst = (which ? kn : qn) + (size_t)t * 2048 + hh * 128;
#pragma unroll
        for (int j = 0; j < 4; j++) {
            int c = cl + j;
            dst[((c & 15) << 3) + (c >> 4)] = v[j] * s;
        }
    } else {
        int i = (b - 16384) * 256 + threadIdx.x;
        int t = i >> 5, hh = i & 31;
        float x  = big[(size_t)t * NPACK + OFF_A + hh] + dtb[hh];
        float sp = (x <= 20.f) ? log1pf(expf(x)) : x;
        egT[(size_t)hh * T_ + t] = expf(-expf(Alg[hh]) * sp);
        float xb = big[(size_t)t * NPACK + OFF_B2 + hh];
        btT[(size_t)hh * T_ + t] = 1.f / (1.f + expf(-xb));
    }
}

// =====================================================================
// one warp per (pair p, hk): q_2p.k_2p, q_2p+1.k_2p+1, k_2p+1.k_2p,
// q_2p+1.k_2p  (dk-permutation is dot-invariant).
// =====================================================================
__global__ void qk_dot3(const float* __restrict__ qn, const float* __restrict__ kn,
                        float* __restrict__ qkd, float* __restrict__ kkx,
                        float* __restrict__ qkx)
{
    int wid  = (blockIdx.x * 256 + threadIdx.x) >> 5;   // 0..16383
    int lane = threadIdx.x & 31;
    int p = wid >> 4, hk = wid & 15;
    int t = p << 1;
    const float* qs = qn + (size_t)t * 2048 + hk * 128 + lane * 4;
    const float* ks = kn + (size_t)t * 2048 + hk * 128 + lane * 4;
    float4 q0 = *(const float4*)qs;
    float4 k0 = *(const float4*)ks;
    float4 q1 = *(const float4*)(qs + 2048);
    float4 k1 = *(const float4*)(ks + 2048);
    float r0 = q0.x * k0.x + q0.y * k0.y + q0.z * k0.z + q0.w * k0.w;
    float r1 = q1.x * k1.x + q1.y * k1.y + q1.z * k1.z + q1.w * k1.w;
    float r2 = k1.x * k0.x + k1.y * k0.y + k1.z * k0.z + k1.w * k0.w;
    float r3 = q1.x * k0.x + q1.y * k0.y + q1.z * k0.z + q1.w * k0.w;
#pragma unroll
    for (int off = 16; off; off >>= 1) {
        r0 += __shfl_xor_sync(0xffffffffu, r0, off);
        r1 += __shfl_xor_sync(0xffffffffu, r1, off);
        r2 += __shfl_xor_sync(0xffffffffu, r2, off);
        r3 += __shfl_xor_sync(0xffffffffu, r3, off);
    }
    if (lane == 0) {
        qkd[(size_t)hk * T_ + t]     = r0;
        qkd[(size_t)hk * T_ + t + 1] = r1;
        kkx[(size_t)hk * 1024 + p]   = r2;
        qkx[(size_t)hk * 1024 + p]   = r3;
    }
}

// =====================================================================
// Gated delta-rule scan v4: exact 2-step lookahead. All 8 reductions
// for a step-pair run against pair-start S0 in ONE butterfly phase.
// Grid (8 dv-tiles, 32 heads), 128 threads, lane = dkg*2+dvg.
// =====================================================================
__global__ __launch_bounds__(128) void gdn_scan(
    const float* __restrict__ qp, const float* __restrict__ kp,
    const float* __restrict__ acts, const float* __restrict__ egT,
    const float* __restrict__ btT, const float* __restrict__ qkd,
    const float* __restrict__ kkx, const float* __restrict__ qkx,
    float* __restrict__ o)
{
    const int h    = blockIdx.y;
    const int dvt  = blockIdx.x;
    const int hk   = h >> 1;
    const int tid  = threadIdx.x;
    const int w    = tid >> 5;
    const int lane = tid & 31;
    const int dkg  = lane >> 1;
    const int dvg  = lane & 1;

    __shared__ float sq[2][32][128];
    __shared__ float sk[2][32][128];
    __shared__ float sv[2][32][16];
    __shared__ float se[2][32];
    __shared__ float sb[2][32];
    __shared__ float sqk[2][32];
    __shared__ float skk[2][16];
    __shared__ float sqx[2][16];

    auto fill = [&](int buf, int t0) {
#pragma unroll
        for (int it = 0; it < 8; it++) {
            int idx = it * 128 + tid;
            int tt = idx >> 5, f = (idx & 31) << 2;
            cp16(smem_u32(&sq[buf][tt][f]), qp + (size_t)(t0 + tt) * 2048 + hk * 128 + f);
            cp16(smem_u32(&sk[buf][tt][f]), kp + (size_t)(t0 + tt) * 2048 + hk * 128 + f);
        }
        {
            int tt = tid >> 2, f = (tid & 3) << 2;
            cp16(smem_u32(&sv[buf][tt][f]),
                 acts + (size_t)(t0 + tt) * 8192 + 4096 + h * 128 + dvt * 16 + f);
        }
        if (tid < 8)
            cp16(smem_u32(&se[buf][tid << 2]), egT + (size_t)h * T_ + t0 + (tid << 2));
        else if (tid < 16)
            cp16(smem_u32(&sb[buf][(tid - 8) << 2]), btT + (size_t)h * T_ + t0 + ((tid - 8) << 2));
        else if (tid < 24)
            cp16(smem_u32(&sqk[buf][(tid - 16) << 2]), qkd + (size_t)hk * T_ + t0 + ((tid - 16) << 2));
        else if (tid < 28)
            cp16(smem_u32(&skk[buf][(tid - 24) << 2]), kkx + (size_t)hk * 1024 + (t0 >> 1) + ((tid - 24) << 2));
        else if (tid < 32)
            cp16(smem_u32(&sqx[buf][(tid - 28) << 2]), qkx + (size_t)hk * 1024 + (t0 >> 1) + ((tid - 28) << 2));
    };

    u64 S2[4][2];
#pragma unroll
    for (int i = 0; i < 4; i++) { S2[i][0] = 0ull; S2[i][1] = 0ull; }

    fill(0, 0); CP_COMMIT();

    for (int c = 0; c < 64; c++) {
        const int buf = c & 1;
        if (c + 1 < 64) { fill(buf ^ 1, (c + 1) << 5); CP_COMMIT(); CP_WAIT(1); }
        else            { CP_WAIT(0); }
        __syncthreads();
#pragma unroll 1
        for (int pp = 0; pp < 16; pp++) {
            const int tt = pp << 1;
            ulonglong2 a0, a1;
            a0 = *(const ulonglong2*)&sk[buf][tt][dkg << 3];
            a1 = *(const ulonglong2*)&sk[buf][tt][(dkg << 3) + 4];
            u64 kt[4]  = {a0.x, a0.y, a1.x, a1.y};
            a0 = *(const ulonglong2*)&sq[buf][tt][dkg << 3];
            a1 = *(const ulonglong2*)&sq[buf][tt][(dkg << 3) + 4];
            u64 qt[4]  = {a0.x, a0.y, a1.x, a1.y};
            a0 = *(const ulonglong2*)&sk[buf][tt + 1][dkg << 3];
            a1 = *(const ulonglong2*)&sk[buf][tt + 1][(dkg << 3) + 4];
            u64 kt1[4] = {a0.x, a0.y, a1.x, a1.y};
            a0 = *(const ulonglong2*)&sq[buf][tt + 1][dkg << 3];
            a1 = *(const ulonglong2*)&sq[buf][tt + 1][(dkg << 3) + 4];
            u64 qt1[4] = {a0.x, a0.y, a1.x, a1.y};
            float2 v0 = *(const float2*)&sv[buf][tt][(w << 2) + (dvg << 1)];
            float2 v1 = *(const float2*)&sv[buf][tt + 1][(w << 2) + (dvg << 1)];
            float e0 = se[buf][tt], e1 = se[buf][tt + 1];
            float b0 = sb[buf][tt], b1 = sb[buf][tt + 1];
            float qk0 = sqk[buf][tt], qk1 = sqk[buf][tt + 1];
            float kk = skk[buf][pp], qx = sqx[buf][pp];

            u64 kv1a = 0ull, kv1b = 0ull, kv2a = 0ull, kv2b = 0ull;
            u64 oq1a = 0ull, oq1b = 0ull, oq2a = 0ull, oq2b = 0ull;
#pragma unroll
            for (int i = 0; i < 4; i++) {
                kv1a = f2fma(kt[i],  S2[i][0], kv1a);
                kv1b = f2fma(kt[i],  S2[i][1], kv1b);
                kv2a = f2fma(kt1[i], S2[i][0], kv2a);
                kv2b = f2fma(kt1[i], S2[i][1], kv2b);
                oq1a = f2fma(qt[i],  S2[i][0], oq1a);
                oq1b = f2fma(qt[i],  S2[i][1], oq1b);
                oq2a = f2fma(qt1[i], S2[i][0], oq2a);
                oq2b = f2fma(qt1[i], S2[i][1], oq2b);
            }
            float r[8] = {f2hadd(kv1a), f2hadd(kv1b), f2hadd(kv2a), f2hadd(kv2b),
                          f2hadd(oq1a), f2hadd(oq1b), f2hadd(oq2a), f2hadd(oq2b)};
#pragma unroll
            for (int m = 2; m <= 16; m <<= 1) {
#pragma unroll
                for (int j = 0; j < 8; j++)
                    r[j] += __shfl_xor_sync(0xffffffffu, r[j], m);
            }
            // step t
            float d0 = b0 * (v0.x - e0 * r[0]);
            float d1 = b0 * (v0.y - e0 * r[1]);
            // step t+1 (lookahead via cross-dots)
            float dn0 = b1 * (v1.x - e1 * fmaf(kk, d0, e0 * r[2]));
            float dn1 = b1 * (v1.y - e1 * fmaf(kk, d1, e0 * r[3]));

            float ee = e0 * e1, ed0 = e1 * d0, ed1 = e1 * d1;
            u64 ee2 = f2b(ee), ed02 = f2b(ed0), ed12 = f2b(ed1);
            u64 dn02 = f2b(dn0), dn12 = f2b(dn1);
#pragma unroll
            for (int i = 0; i < 4; i++) {
                S2[i][0] = f2fma(S2[i][0], ee2, f2fma(kt1[i], dn02, f2mul(kt[i], ed02)));
                S2[i][1] = f2fma(S2[i][1], ee2, f2fma(kt1[i], dn12, f2mul(kt[i], ed12)));
            }
            if (dkg == 0) {
                float2 o0 = make_float2(fmaf(qk0, d0, e0 * r[4]),
                                        fmaf(qk0, d1, e0 * r[5]));
                float2 o1 = make_float2(fmaf(qk1, dn0, e1 * fmaf(qx, d0, e0 * r[6])),
                                        fmaf(qk1, dn1, e1 * fmaf(qx, d1, e0 * r[7])));
                size_t ob = (size_t)((c << 5) + tt) * 4096 + h * 128
                          + dvt * 16 + (w << 2) + (dvg << 1);
                *(float2*)(o + ob) = o0;
                *(float2*)(o + ob + 4096) = o1;
            }
        }
        __syncthreads();
    }
}

// ============ gated RMSNorm + silu(gate), fp16 output ============
__global__ void gate_norm(const float* __restrict__ o, const float* __restrict__ big,
                          const float* __restrict__ wn, __half* __restrict__ og)
{
    int wid  = (blockIdx.x * blockDim.x + threadIdx.x) >> 5;
    int lane = threadIdx.x & 31;
    int t = wid >> 5;
    int h = wid & 31;
    size_t base = (size_t)t * 4096 + h * 128 + lane * 4;
    float4 x = *(const float4*)(o + base);
    float ss = x.x * x.x + x.y * x.y + x.z * x.z + x.w * x.w;
#pragma unroll
    for (int off = 16; off; off >>= 1) ss += __shfl_xor_sync(0xffffffffu, ss, off);
    float r = rsqrtf(ss * (1.f / 128.f) + 1e-5f);
    float4 gv = *(const float4*)(big + (size_t)t * NPACK + OFF_G + h * 128 + lane * 4);
    float4 wv = *(const float4*)(wn + lane * 4);
    float ox = x.x * r * wv.x * (gv.x / (1.f + expf(-gv.x)));
    float oy = x.y * r * wv.y * (gv.y / (1.f + expf(-gv.y)));
    float oz = x.z * r * wv.z * (gv.z / (1.f + expf(-gv.z)));
    float ow = x.w * r * wv.w * (gv.w / (1.f + expf(-gv.w)));
    *(__half2*)(og + base + 0) = __floats2half2_rn(ox, oy);
    *(__half2*)(og + base + 2) = __floats2half2_rn(oz, ow);
}

// =====================================================================
extern "C" void kernel_launch(void* const* d_in, const int* in_sizes, int n_in,
                              void* d_out, int out_size)
{
    const float* h   = (const float*)d_in[0];
    const float* Wq  = (const float*)d_in[1];
    const float* Wk  = (const float*)d_in[2];
    const float* Wv  = (const float*)d_in[3];
    const float* Wa  = (const float*)d_in[4];
    const float* Wb  = (const float*)d_in[5];
    const float* Wg  = (const float*)d_in[6];
    const float* cq  = (const float*)d_in[7];
    const float* ck  = (const float*)d_in[8];
    const float* cv  = (const float*)d_in[9];
    const float* dtb = (const float*)d_in[10];
    const float* Alg = (const float*)d_in[11];
    const float* onw = (const float*)d_in[12];
    const float* Wo  = (const float*)d_in[13];
    float* out = (float*)d_out;

    float *big, *acts, *egT, *btT, *qn, *kn, *qkd, *kkx, *qkx, *o;
    __half *Wp, *hr, *WoR, *og;
    cudaGetSymbolAddress((void**)&big,  g_big);
    cudaGetSymbolAddress((void**)&Wp,   g_Wp);
    cudaGetSymbolAddress((void**)&hr,   g_hr);
    cudaGetSymbolAddress((void**)&WoR,  g_WoR);
    cudaGetSymbolAddress((void**)&acts, g_acts);
    cudaGetSymbolAddress((void**)&egT,  g_egT);
    cudaGetSymbolAddress((void**)&btT,  g_btT);
    cudaGetSymbolAddress((void**)&qn,   g_qn);
    cudaGetSymbolAddress((void**)&kn,   g_kn);
    cudaGetSymbolAddress((void**)&qkd,  g_qkd);
    cudaGetSymbolAddress((void**)&kkx,  g_kkx);
    cudaGetSymbolAddress((void**)&qkx,  g_qkx);
    cudaGetSymbolAddress((void**)&o,    g_o);
    cudaGetSymbolAddress((void**)&og,   g_og);

    cudaFuncSetAttribute(mma_gemm, cudaFuncAttributeMaxDynamicSharedMemorySize, GEMM_SMEM);

    half_copy<<<(2048 * 2048 / 4) / 256, 256>>>(h, hr);
    pack_w<<<2048 * 3136 / 256, 256>>>(Wq, Wk, Wv, Wg, Wa, Wb, Wp);

    mma_gemm<<<dim3(8, 98), 512, GEMM_SMEM>>>(hr, Wp, big, 2048, NPACK, NPACK);

    conv_norm<<<16640, 256>>>(big, cq, ck, cv, dtb, Alg, acts, egT, btT, qn, kn);
    qk_dot3<<<2048, 256>>>(qn, kn, qkd, kkx, qkx);
    gdn_scan<<<dim3(8, 32), 128>>>(qn, kn, acts, egT, btT, qkd, kkx, qkx, o);
    gate_norm<<<8192, 256>>>(o, big, onw, og);

    half_copy<<<(4096 * 2048 / 4) / 256, 256>>>(Wo, WoR);
    mma_gemm<<<dim3(8, 16), 512, GEMM_SMEM>>>(og, WoR, out, 4096, 2048, 2048);
}

// round 15
// speedup vs baseline: 1.0034x; 1.0034x over previous
#include <cuda_runtime.h>
#include <cuda_fp16.h>
#include <math.h>
#include <cstdint>

static constexpr int T_   = 2048;
static constexpr int NH   = 32;
static constexpr int NPACK = 12544;
static constexpr int OFF_K = 2048;
static constexpr int OFF_V = 4096;
static constexpr int OFF_G = 8192;
static constexpr int OFF_A = 12288;
static constexpr int OFF_B2 = 12320;
static constexpr int OFF_END = 12352;

__device__ float  g_big [T_ * NPACK];
__device__ __half g_Wp  [2048 * NPACK];   // packed fp16 weights
__device__ __half g_hr  [T_ * 2048];      // fp16 h
__device__ __half g_WoR [4096 * 2048];    // fp16 Wo
__device__ __half g_og  [T_ * 4096];      // fp16 normed+gated
__device__ float  g_acts[T_ * 8192];      // only v region [4096,8192) used
__device__ float  g_egT [NH * T_];
__device__ float  g_btT [NH * T_];
__device__ float  g_qn  [T_ * 2048];      // l2-normed q, dk-permuted rows
__device__ float  g_kn  [T_ * 2048];
__device__ float  g_qkd [16 * T_];        // q_t . k_t        [hk][t]
__device__ float  g_kkx [16 * 1024];      // k_{2p+1} . k_2p  [hk][p]
__device__ float  g_qkx [16 * 1024];      // q_{2p+1} . k_2p  [hk][p]
__device__ float  g_o   [T_ * 4096];

__device__ __forceinline__ uint32_t smem_u32(const void* p) {
    uint32_t a;
    asm("{ .reg .u64 t; cvta.to.shared.u64 t, %1; cvt.u32.u64 %0, t; }" : "=r"(a) : "l"(p));
    return a;
}
__device__ __forceinline__ void cp16(uint32_t dst, const void* src) {
    asm volatile("cp.async.cg.shared.global [%0], [%1], 16;" :: "r"(dst), "l"(src));
}
#define CP_COMMIT() asm volatile("cp.async.commit_group;" ::: "memory")
#define CP_WAIT(n)  asm volatile("cp.async.wait_group %0;" :: "n"(n) : "memory")

__device__ __forceinline__ void ldsm_x4(uint32_t addr, uint32_t* r) {
    asm volatile("ldmatrix.sync.aligned.m8n8.x4.shared.b16 {%0,%1,%2,%3}, [%4];"
        : "=r"(r[0]), "=r"(r[1]), "=r"(r[2]), "=r"(r[3]) : "r"(addr));
}
__device__ __forceinline__ void ldsm_x2t(uint32_t addr, uint32_t* r) {
    asm volatile("ldmatrix.sync.aligned.m8n8.x2.trans.shared.b16 {%0,%1}, [%2];"
        : "=r"(r[0]), "=r"(r[1]) : "r"(addr));
}
__device__ __forceinline__ void mma_f16(float* c, const uint32_t* a, const uint32_t* b) {
    asm volatile("mma.sync.aligned.m16n8k16.row.col.f32.f16.f16.f32 "
        "{%0,%1,%2,%3}, {%4,%5,%6,%7}, {%8,%9}, {%0,%1,%2,%3};"
        : "+f"(c[0]), "+f"(c[1]), "+f"(c[2]), "+f"(c[3])
        : "r"(a[0]), "r"(a[1]), "r"(a[2]), "r"(a[3]), "r"(b[0]), "r"(b[1]));
}

// ---- packed f32x2 helpers (sm_100+ base ISA) ----
typedef unsigned long long u64;
__device__ __forceinline__ u64 f2b(float x) {
    u64 r; asm("mov.b64 %0, {%1, %1};" : "=l"(r) : "f"(x)); return r;
}
__device__ __forceinline__ float f2hadd(u64 v) {
    float a, b; asm("mov.b64 {%0, %1}, %2;" : "=f"(a), "=f"(b) : "l"(v)); return a + b;
}
__device__ __forceinline__ u64 f2fma(u64 a, u64 b, u64 c) {
    u64 d; asm("fma.rn.f32x2 %0, %1, %2, %3;" : "=l"(d) : "l"(a), "l"(b), "l"(c)); return d;
}
__device__ __forceinline__ u64 f2mul(u64 a, u64 b) {
    u64 d; asm("mul.rn.f32x2 %0, %1, %2;" : "=l"(d) : "l"(a), "l"(b)); return d;
}

// =====================================================================
// fp16 mma.sync GEMM (unchanged from R12, proven).
// =====================================================================
static constexpr uint32_t STAGE = 49152;
static constexpr uint32_t GEMM_SMEM = 4 * STAGE;   // 192KB

__global__ __launch_bounds__(512, 1) void mma_gemm(
    const __half* __restrict__ A, const __half* __restrict__ B, float* __restrict__ C,
    int K, int ldb, int ldc)
{
    extern __shared__ char smem[];
    const uint32_t sbase = smem_u32(smem);
    const int tid  = threadIdx.x;
    const int lane = tid & 31;
    const int w    = tid >> 5;
    const int wm   = w >> 2;
    const int wn   = w & 3;
    const int c4   = lane & 3;
    const int g    = lane >> 2;
    const int row0 = blockIdx.x * 256;
    const int col0 = blockIdx.y * 128;
    const int mA   = lane >> 3;
    const int iA   = lane & 7;

    float acc[4][4][4];
#pragma unroll
    for (int mi = 0; mi < 4; mi++)
#pragma unroll
        for (int ni = 0; ni < 4; ni++)
#pragma unroll
            for (int q = 0; q < 4; q++) acc[mi][ni][q] = 0.f;

    const int nt = K >> 6;

    auto issue = [&](int t, int st) {
        const int k0 = t << 6;
        const uint32_t sA = sbase + st * STAGE;
        const uint32_t sB = sA + 32768;
#pragma unroll
        for (int it = 0; it < 4; it++) {
            int idx = it * 512 + tid;
            int r = idx >> 3, f = idx & 7;
            cp16(sA + r * 128 + (((uint32_t)(f ^ (r & 7))) << 4),
                 A + (size_t)(row0 + r) * K + k0 + f * 8);
        }
#pragma unroll
        for (int it = 0; it < 2; it++) {
            int idx = it * 512 + tid;
            int k = idx >> 4, cn = idx & 15;
            cp16(sB + k * 256 + (((uint32_t)(cn ^ (k & 7))) << 4),
                 B + (size_t)(k0 + k) * ldb + col0 + cn * 8);
        }
    };

    auto compute = [&](int st) {
        const uint32_t sA = sbase + st * STAGE;
        const uint32_t sB = sA + 32768;
#pragma unroll
        for (int s = 0; s < 4; s++) {
            uint32_t af[4][4];
            uint32_t bf[4][2];
#pragma unroll
            for (int mi = 0; mi < 4; mi++) {
                int row = wm * 64 + mi * 16 + iA + ((mA & 1) << 3);
                int f = 2 * s + (mA >> 1);
                ldsm_x4(sA + row * 128 + (((uint32_t)(f ^ (row & 7))) << 4), af[mi]);
            }
#pragma unroll
            for (int ni = 0; ni < 4; ni++) {
                int cn = 4 * wn + ni;
                int k = 16 * s + ((mA & 1) << 3) + iA;
                ldsm_x2t(sB + k * 256 + (((uint32_t)(cn ^ (k & 7))) << 4), bf[ni]);
            }
#pragma unroll
            for (int mi = 0; mi < 4; mi++)
#pragma unroll
                for (int ni = 0; ni < 4; ni++)
                    mma_f16(acc[mi][ni], af[mi], bf[ni]);
        }
    };

    issue(0, 0); CP_COMMIT();
    issue(1, 1); CP_COMMIT();
    issue(2, 2); CP_COMMIT();
    int st = 0;
    for (int t = 0; t < nt; t++) {
        if (t + 3 < nt) {
            CP_WAIT(2);
            __syncthreads();
            issue(t + 3, (st + 3) & 3);
            CP_COMMIT();
        } else {
            CP_WAIT(0);
            __syncthreads();
        }
        compute(st);
        st = (st + 1) & 3;
    }

#pragma unroll
    for (int mi = 0; mi < 4; mi++) {
        const int r0 = row0 + wm * 64 + mi * 16 + g;
#pragma unroll
        for (int ni = 0; ni < 4; ni++) {
            const int cc = col0 + wn * 32 + ni * 8 + 2 * c4;
            *(float2*)(C + (size_t)r0 * ldc + cc) =
                make_float2(acc[mi][ni][0], acc[mi][ni][1]);
            *(float2*)(C + (size_t)(r0 + 8) * ldc + cc) =
                make_float2(acc[mi][ni][2], acc[mi][ni][3]);
        }
    }
}

// ================= weight pack (fp16) =================
__global__ void pack_w(const float* __restrict__ Wq, const float* __restrict__ Wk,
                       const float* __restrict__ Wv, const float* __restrict__ Wg,
                       const float* __restrict__ Wa, const float* __restrict__ Wb,
                       __half* __restrict__ P)
{
    int idx = blockIdx.x * 256 + threadIdx.x;
    int k = idx / 3136;
    int n = (idx - k * 3136) * 4;
    float4 v = make_float4(0.f, 0.f, 0.f, 0.f);
    if      (n < OFF_K)   v = *(const float4*)(Wq + (size_t)k * 2048 + n);
    else if (n < OFF_V)   v = *(const float4*)(Wk + (size_t)k * 2048 + n - OFF_K);
    else if (n < OFF_G)   v = *(const float4*)(Wv + (size_t)k * 4096 + n - OFF_V);
    else if (n < OFF_A)   v = *(const float4*)(Wg + (size_t)k * 4096 + n - OFF_G);
    else if (n < OFF_B2)  v = *(const float4*)(Wa + (size_t)k * 32 + n - OFF_A);
    else if (n < OFF_END) v = *(const float4*)(Wb + (size_t)k * 32 + n - OFF_B2);
    __half* p = P + (size_t)k * NPACK + n;
    *(__half2*)(p + 0) = __floats2half2_rn(v.x, v.y);
    *(__half2*)(p + 2) = __floats2half2_rn(v.z, v.w);
}

// float -> fp16 copy
__global__ void half_copy(const float* __restrict__ src, __half* __restrict__ dst)
{
    int i = (blockIdx.x * 256 + threadIdx.x) * 4;
    float4 v = *(const float4*)(src + i);
    *(__half2*)(dst + i + 0) = __floats2half2_rn(v.x, v.y);
    *(__half2*)(dst + i + 2) = __floats2half2_rn(v.z, v.w);
}

// =====================================================================
// Fused: v-conv+SiLU; q/k conv+SiLU+l2norm+permute; gate/beta (as R12).
// =====================================================================
__global__ void conv_norm(const float* __restrict__ big,
                          const float* __restrict__ cq, const float* __restrict__ ck,
                          const float* __restrict__ cv, const float* __restrict__ dtb,
                          const float* __restrict__ Alg, float* __restrict__ acts,
                          float* __restrict__ egT, float* __restrict__ btT,
                          float* __restrict__ qn, float* __restrict__ kn)
{
    int b = blockIdx.x;
    float4 z = make_float4(0.f, 0.f, 0.f, 0.f);
    if (b < 8192) {
        int gid = b * 256 + threadIdx.x;
        int t = gid >> 10;
        int c = (gid & 1023) << 2;
        const float* wp = cv + c * 4;
        float4 w0 = *(const float4*)(wp + 0), w1 = *(const float4*)(wp + 4);
        float4 w2 = *(const float4*)(wp + 8), w3 = *(const float4*)(wp + 12);
        const float* xp = big + (size_t)t * NPACK + 4096 + c;
        float4 x3 = *(const float4*)xp;
        float4 x2 = (t >= 1) ? *(const float4*)(xp - NPACK)     : z;
        float4 x1 = (t >= 2) ? *(const float4*)(xp - 2 * NPACK) : z;
        float4 x0 = (t >= 3) ? *(const float4*)(xp - 3 * NPACK) : z;
        float4 o;
        o.x = w0.x * x0.x + w0.y * x1.x + w0.z * x2.x + w0.w * x3.x;
        o.y = w1.x * x0.y + w1.y * x1.y + w1.z * x2.y + w1.w * x3.y;
        o.z = w2.x * x0.z + w2.y * x1.z + w2.z * x2.z + w2.w * x3.z;
        o.w = w3.x * x0.w + w3.y * x1.w + w3.z * x2.w + w3.w * x3.w;
        o.x = o.x / (1.f + expf(-o.x)); o.y = o.y / (1.f + expf(-o.y));
        o.z = o.z / (1.f + expf(-o.z)); o.w = o.w / (1.f + expf(-o.w));
        *(float4*)(acts + (size_t)t * 8192 + 4096 + c) = o;
    } else if (b < 16384) {
        int gw   = (b - 8192) * 8 + (threadIdx.x >> 5);
        int lane = threadIdx.x & 31;
        int t     = gw >> 5;
        int rest  = gw & 31;
        int which = rest & 1;
        int hh    = rest >> 1;
        int cl    = lane * 4;
        const float* wp = (which ? ck : cq) + (hh * 128 + cl) * 4;
        float4 w0 = *(const float4*)(wp + 0), w1 = *(const float4*)(wp + 4);
        float4 w2 = *(const float4*)(wp + 8), w3 = *(const float4*)(wp + 12);
        const float* xp = big + (size_t)t * NPACK + which * 2048 + hh * 128 + cl;
        float4 x3 = *(const float4*)xp;
        float4 x2 = (t >= 1) ? *(const float4*)(xp - NPACK)     : z;
        float4 x1 = (t >= 2) ? *(const float4*)(xp - 2 * NPACK) : z;
        float4 x0 = (t >= 3) ? *(const float4*)(xp - 3 * NPACK) : z;
        float v[4];
        v[0] = w0.x * x0.x + w0.y * x1.x + w0.z * x2.x + w0.w * x3.x;
        v[1] = w1.x * x0.y + w1.y * x1.y + w1.z * x2.y + w1.w * x3.y;
        v[2] = w2.x * x0.z + w2.y * x1.z + w2.z * x2.z + w2.w * x3.z;
        v[3] = w3.x * x0.w + w3.y * x1.w + w3.z * x2.w + w3.w * x3.w;
#pragma unroll
        for (int j = 0; j < 4; j++) v[j] = v[j] / (1.f + expf(-v[j]));
        float ss = v[0] * v[0] + v[1] * v[1] + v[2] * v[2] + v[3] * v[3];
#pragma unroll
        for (int off = 16; off; off >>= 1) ss += __shfl_xor_sync(0xffffffffu, ss, off);
        float s = rsqrtf(ss + 1e-6f);
        if (which == 0) s *= 0.08838834764831845f;
        float* dst = (which ? kn : qn) + (size_t)t * 2048 + hh * 128;
#pragma unroll
        for (int j = 0; j < 4; j++) {
            int c = cl + j;
            dst[((c & 15) << 3) + (c >> 4)] = v[j] * s;
        }
    } else {
        int i = (b - 16384) * 256 + threadIdx.x;
        int t = i >> 5, hh = i & 31;
        float x  = big[(size_t)t * NPACK + OFF_A + hh] + dtb[hh];
        float sp = (x <= 20.f) ? log1pf(expf(x)) : x;
        egT[(size_t)hh * T_ + t] = expf(-expf(Alg[hh]) * sp);
        float xb = big[(size_t)t * NPACK + OFF_B2 + hh];
        btT[(size_t)hh * T_ + t] = 1.f / (1.f + expf(-xb));
    }
}

// =====================================================================
// one warp per (pair p, hk): q_2p.k_2p, q_2p+1.k_2p+1, k_2p+1.k_2p,
// q_2p+1.k_2p  (dk-permutation is dot-invariant).
// =====================================================================
__global__ void qk_dot3(const float* __restrict__ qn, const float* __restrict__ kn,
                        float* __restrict__ qkd, float* __restrict__ kkx,
                        float* __restrict__ qkx)
{
    int wid  = (blockIdx.x * 256 + threadIdx.x) >> 5;   // 0..16383
    int lane = threadIdx.x & 31;
    int p = wid >> 4, hk = wid & 15;
    int t = p << 1;
    const float* qs = qn + (size_t)t * 2048 + hk * 128 + lane * 4;
    const float* ks = kn + (size_t)t * 2048 + hk * 128 + lane * 4;
    float4 q0 = *(const float4*)qs;
    float4 k0 = *(const float4*)ks;
    float4 q1 = *(const float4*)(qs + 2048);
    float4 k1 = *(const float4*)(ks + 2048);
    float r0 = q0.x * k0.x + q0.y * k0.y + q0.z * k0.z + q0.w * k0.w;
    float r1 = q1.x * k1.x + q1.y * k1.y + q1.z * k1.z + q1.w * k1.w;
    float r2 = k1.x * k0.x + k1.y * k0.y + k1.z * k0.z + k1.w * k0.w;
    float r3 = q1.x * k0.x + q1.y * k0.y + q1.z * k0.z + q1.w * k0.w;
#pragma unroll
    for (int off = 16; off; off >>= 1) {
        r0 += __shfl_xor_sync(0xffffffffu, r0, off);
        r1 += __shfl_xor_sync(0xffffffffu, r1, off);
        r2 += __shfl_xor_sync(0xffffffffu, r2, off);
        r3 += __shfl_xor_sync(0xffffffffu, r3, off);
    }
    if (lane == 0) {
        qkd[(size_t)hk * T_ + t]     = r0;
        qkd[(size_t)hk * T_ + t + 1] = r1;
        kkx[(size_t)hk * 1024 + p]   = r2;
        qkx[(size_t)hk * 1024 + p]   = r3;
    }
}

// =====================================================================
// Gated delta-rule scan v4: exact 2-step lookahead. All 8 reductions
// for a step-pair run against pair-start S0 in ONE butterfly phase.
// Grid (8 dv-tiles, 32 heads), 128 threads, lane = dkg*2+dvg.
// =====================================================================
__global__ __launch_bounds__(128) void gdn_scan(
    const float* __restrict__ qp, const float* __restrict__ kp,
    const float* __restrict__ acts, const float* __restrict__ egT,
    const float* __restrict__ btT, const float* __restrict__ qkd,
    const float* __restrict__ kkx, const float* __restrict__ qkx,
    float* __restrict__ o)
{
    const int h    = blockIdx.y;
    const int dvt  = blockIdx.x;
    const int hk   = h >> 1;
    const int tid  = threadIdx.x;
    const int w    = tid >> 5;
    const int lane = tid & 31;
    const int dkg  = lane >> 1;
    const int dvg  = lane & 1;

    __shared__ float sq[2][32][128];
    __shared__ float sk[2][32][128];
    __shared__ float sv[2][32][16];
    __shared__ float se[2][32];
    __shared__ float sb[2][32];
    __shared__ float sqk[2][32];
    __shared__ float skk[2][16];
    __shared__ float sqx[2][16];

    auto fill = [&](int buf, int t0) {
#pragma unroll
        for (int it = 0; it < 8; it++) {
            int idx = it * 128 + tid;
            int tt = idx >> 5, f = (idx & 31) << 2;
            cp16(smem_u32(&sq[buf][tt][f]), qp + (size_t)(t0 + tt) * 2048 + hk * 128 + f);
            cp16(smem_u32(&sk[buf][tt][f]), kp + (size_t)(t0 + tt) * 2048 + hk * 128 + f);
        }
        {
            int tt = tid >> 2, f = (tid & 3) << 2;
            cp16(smem_u32(&sv[buf][tt][f]),
                 acts + (size_t)(t0 + tt) * 8192 + 4096 + h * 128 + dvt * 16 + f);
        }
        if (tid < 8)
            cp16(smem_u32(&se[buf][tid << 2]), egT + (size_t)h * T_ + t0 + (tid << 2));
        else if (tid < 16)
            cp16(smem_u32(&sb[buf][(tid - 8) << 2]), btT + (size_t)h * T_ + t0 + ((tid - 8) << 2));
        else if (tid < 24)
            cp16(smem_u32(&sqk[buf][(tid - 16) << 2]), qkd + (size_t)hk * T_ + t0 + ((tid - 16) << 2));
        else if (tid < 28)
            cp16(smem_u32(&skk[buf][(tid - 24) << 2]), kkx + (size_t)hk * 1024 + (t0 >> 1) + ((tid - 24) << 2));
        else if (tid < 32)
            cp16(smem_u32(&sqx[buf][(tid - 28) << 2]), qkx + (size_t)hk * 1024 + (t0 >> 1) + ((tid - 28) << 2));
    };

    u64 S2[4][2];
#pragma unroll
    for (int i = 0; i < 4; i++) { S2[i][0] = 0ull; S2[i][1] = 0ull; }

    fill(0, 0); CP_COMMIT();

    for (int c = 0; c < 64; c++) {
        const int buf = c & 1;
        if (c + 1 < 64) { fill(buf ^ 1, (c + 1) << 5); CP_COMMIT(); CP_WAIT(1); }
        else            { CP_WAIT(0); }
        __syncthreads();
#pragma unroll 1
        for (int pp = 0; pp < 16; pp++) {
            const int tt = pp << 1;
            ulonglong2 a0, a1;
            a0 = *(const ulonglong2*)&sk[buf][tt][dkg << 3];
            a1 = *(const ulonglong2*)&sk[buf][tt][(dkg << 3) + 4];
            u64 kt[4]  = {a0.x, a0.y, a1.x, a1.y};
            a0 = *(const ulonglong2*)&sq[buf][tt][dkg << 3];
            a1 = *(const ulonglong2*)&sq[buf][tt][(dkg << 3) + 4];
            u64 qt[4]  = {a0.x, a0.y, a1.x, a1.y};
            a0 = *(const ulonglong2*)&sk[buf][tt + 1][dkg << 3];
            a1 = *(const ulonglong2*)&sk[buf][tt + 1][(dkg << 3) + 4];
            u64 kt1[4] = {a0.x, a0.y, a1.x, a1.y};
            a0 = *(const ulonglong2*)&sq[buf][tt + 1][dkg << 3];
            a1 = *(const ulonglong2*)&sq[buf][tt + 1][(dkg << 3) + 4];
            u64 qt1[4] = {a0.x, a0.y, a1.x, a1.y};
            float2 v0 = *(const float2*)&sv[buf][tt][(w << 2) + (dvg << 1)];
            float2 v1 = *(const float2*)&sv[buf][tt + 1][(w << 2) + (dvg << 1)];
            float e0 = se[buf][tt], e1 = se[buf][tt + 1];
            float b0 = sb[buf][tt], b1 = sb[buf][tt + 1];
            float qk0 = sqk[buf][tt], qk1 = sqk[buf][tt + 1];
            float kk = skk[buf][pp], qx = sqx[buf][pp];

            u64 kv1a = 0ull, kv1b = 0ull, kv2a = 0ull, kv2b = 0ull;
            u64 oq1a = 0ull, oq1b = 0ull, oq2a = 0ull, oq2b = 0ull;
#pragma unroll
            for (int i = 0; i < 4; i++) {
                kv1a = f2fma(kt[i],  S2[i][0], kv1a);
                kv1b = f2fma(kt[i],  S2[i][1], kv1b);
                kv2a = f2fma(kt1[i], S2[i][0], kv2a);
                kv2b = f2fma(kt1[i], S2[i][1], kv2b);
                oq1a = f2fma(qt[i],  S2[i][0], oq1a);
                oq1b = f2fma(qt[i],  S2[i][1], oq1b);
                oq2a = f2fma(qt1[i], S2[i][0], oq2a);
                oq2b = f2fma(qt1[i], S2[i][1], oq2b);
            }
            float r[8] = {f2hadd(kv1a), f2hadd(kv1b), f2hadd(kv2a), f2hadd(kv2b),
                          f2hadd(oq1a), f2hadd(oq1b), f2hadd(oq2a), f2hadd(oq2b)};
#pragma unroll
            for (int m = 2; m <= 16; m <<= 1) {
#pragma unroll
                for (int j = 0; j < 8; j++)
                    r[j] += __shfl_xor_sync(0xffffffffu, r[j], m);
            }
            // step t
            float d0 = b0 * (v0.x - e0 * r[0]);
            float d1 = b0 * (v0.y - e0 * r[1]);
            // step t+1 (lookahead via cross-dots)
            float dn0 = b1 * (v1.x - e1 * fmaf(kk, d0, e0 * r[2]));
            float dn1 = b1 * (v1.y - e1 * fmaf(kk, d1, e0 * r[3]));

            float ee = e0 * e1, ed0 = e1 * d0, ed1 = e1 * d1;
            u64 ee2 = f2b(ee), ed02 = f2b(ed0), ed12 = f2b(ed1);
            u64 dn02 = f2b(dn0), dn12 = f2b(dn1);
#pragma unroll
            for (int i = 0; i < 4; i++) {
                S2[i][0] = f2fma(S2[i][0], ee2, f2fma(kt1[i], dn02, f2mul(kt[i], ed02)));
                S2[i][1] = f2fma(S2[i][1], ee2, f2fma(kt1[i], dn12, f2mul(kt[i], ed12)));
            }
            if (dkg == 0) {
                float2 o0 = make_float2(fmaf(qk0, d0, e0 * r[4]),
                                        fmaf(qk0, d1, e0 * r[5]));
                float2 o1 = make_float2(fmaf(qk1, dn0, e1 * fmaf(qx, d0, e0 * r[6])),
                                        fmaf(qk1, dn1, e1 * fmaf(qx, d1, e0 * r[7])));
                size_t ob = (size_t)((c << 5) + tt) * 4096 + h * 128
                          + dvt * 16 + (w << 2) + (dvg << 1);
                *(float2*)(o + ob) = o0;
                *(float2*)(o + ob + 4096) = o1;
            }
        }
        __syncthreads();
    }
}

// ============ gated RMSNorm + silu(gate), fp16 output ============
__global__ void gate_norm(const float* __restrict__ o, const float* __restrict__ big,
                          const float* __restrict__ wn, __half* __restrict__ og)
{
    int wid  = (blockIdx.x * blockDim.x + threadIdx.x) >> 5;
    int lane = threadIdx.x & 31;
    int t = wid >> 5;
    int h = wid & 31;
    size_t base = (size_t)t * 4096 + h * 128 + lane * 4;
    float4 x = *(const float4*)(o + base);
    float ss = x.x * x.x + x.y * x.y + x.z * x.z + x.w * x.w;
#pragma unroll
    for (int off = 16; off; off >>= 1) ss += __shfl_xor_sync(0xffffffffu, ss, off);
    float r = rsqrtf(ss * (1.f / 128.f) + 1e-5f);
    float4 gv = *(const float4*)(big + (size_t)t * NPACK + OFF_G + h * 128 + lane * 4);
    float4 wv = *(const float4*)(wn + lane * 4);
    float ox = x.x * r * wv.x * (gv.x / (1.f + expf(-gv.x)));
    float oy = x.y * r * wv.y * (gv.y / (1.f + expf(-gv.y)));
    float oz = x.z * r * wv.z * (gv.z / (1.f + expf(-gv.z)));
    float ow = x.w * r * wv.w * (gv.w / (1.f + expf(-gv.w)));
    *(__half2*)(og + base + 0) = __floats2half2_rn(ox, oy);
    *(__half2*)(og + base + 2) = __floats2half2_rn(oz, ow);
}

// =====================================================================
extern "C" void kernel_launch(void* const* d_in, const int* in_sizes, int n_in,
                              void* d_out, int out_size)
{
    const float* h   = (const float*)d_in[0];
    const float* Wq  = (const float*)d_in[1];
    const float* Wk  = (const float*)d_in[2];
    const float* Wv  = (const float*)d_in[3];
    const float* Wa  = (const float*)d_in[4];
    const float* Wb  = (const float*)d_in[5];
    const float* Wg  = (const float*)d_in[6];
    const float* cq  = (const float*)d_in[7];
    const float* ck  = (const float*)d_in[8];
    const float* cv  = (const float*)d_in[9];
    const float* dtb = (const float*)d_in[10];
    const float* Alg = (const float*)d_in[11];
    const float* onw = (const float*)d_in[12];
    const float* Wo  = (const float*)d_in[13];
    float* out = (float*)d_out;

    float *big, *acts, *egT, *btT, *qn, *kn, *qkd, *kkx, *qkx, *o;
    __half *Wp, *hr, *WoR, *og;
    cudaGetSymbolAddress((void**)&big,  g_big);
    cudaGetSymbolAddress((void**)&Wp,   g_Wp);
    cudaGetSymbolAddress((void**)&hr,   g_hr);
    cudaGetSymbolAddress((void**)&WoR,  g_WoR);
    cudaGetSymbolAddress((void**)&acts, g_acts);
    cudaGetSymbolAddress((void**)&egT,  g_egT);
    cudaGetSymbolAddress((void**)&btT,  g_btT);
    cudaGetSymbolAddress((void**)&qn,   g_qn);
    cudaGetSymbolAddress((void**)&kn,   g_kn);
    cudaGetSymbolAddress((void**)&qkd,  g_qkd);
    cudaGetSymbolAddress((void**)&kkx,  g_kkx);
    cudaGetSymbolAddress((void**)&qkx,  g_qkx);
    cudaGetSymbolAddress((void**)&o,    g_o);
    cudaGetSymbolAddress((void**)&og,   g_og);

    cudaFuncSetAttribute(mma_gemm, cudaFuncAttributeMaxDynamicSharedMemorySize, GEMM_SMEM);

    half_copy<<<(2048 * 2048 / 4) / 256, 256>>>(h, hr);
    pack_w<<<2048 * 3136 / 256, 256>>>(Wq, Wk, Wv, Wg, Wa, Wb, Wp);

    mma_gemm<<<dim3(8, 98), 512, GEMM_SMEM>>>(hr, Wp, big, 2048, NPACK, NPACK);

    conv_norm<<<16640, 256>>>(big, cq, ck, cv, dtb, Alg, acts, egT, btT, qn, kn);
    qk_dot3<<<2048, 256>>>(qn, kn, qkd, kkx, qkx);
    gdn_scan<<<dim3(8, 32), 128>>>(qn, kn, acts, egT, btT, qkd, kkx, qkx, o);
    gate_norm<<<8192, 256>>>(o, big, onw, og);

    half_copy<<<(4096 * 2048 / 4) / 256, 256>>>(Wo, WoR);
    mma_gemm<<<dim3(8, 16), 512, GEMM_SMEM>>>(og, WoR, out, 4096, 2048, 2048);
}

// round 16
// speedup vs baseline: 1.0192x; 1.0157x over previous
#include <cuda_runtime.h>
#include <cuda_fp16.h>
#include <math.h>
#include <cstdint>

static constexpr int T_   = 2048;
static constexpr int NH   = 32;
static constexpr int NPACK = 12544;
static constexpr int OFF_K = 2048;
static constexpr int OFF_V = 4096;
static constexpr int OFF_G = 8192;
static constexpr int OFF_A = 12288;
static constexpr int OFF_B2 = 12320;
static constexpr int OFF_END = 12352;

__device__ float  g_big [T_ * NPACK];
__device__ __half g_Wp  [2048 * NPACK];   // packed fp16 weights
__device__ __half g_hr  [T_ * 2048];      // fp16 h
__device__ __half g_WoR [4096 * 2048];    // fp16 Wo
__device__ __half g_og  [T_ * 4096];      // fp16 normed+gated
__device__ float  g_acts[T_ * 8192];      // only v region [4096,8192) used
__device__ float  g_egT [NH * T_];
__device__ float  g_btT [NH * T_];
__device__ float  g_qn  [T_ * 2048];      // l2-normed q, dk-permuted rows
__device__ float  g_kn  [T_ * 2048];
__device__ float  g_qkd [16 * T_];        // q_t . k_t        [hk][t]
__device__ float  g_kkx [16 * 1024];      // k_{2p+1} . k_2p  [hk][p]
__device__ float  g_qkx [16 * 1024];      // q_{2p+1} . k_2p  [hk][p]
__device__ float  g_o   [T_ * 4096];

__device__ __forceinline__ float fsilu(float x) {
    return x * __fdividef(1.f, 1.f + __expf(-x));
}
__device__ __forceinline__ float fsigm(float x) {
    return __fdividef(1.f, 1.f + __expf(-x));
}

__device__ __forceinline__ uint32_t smem_u32(const void* p) {
    uint32_t a;
    asm("{ .reg .u64 t; cvta.to.shared.u64 t, %1; cvt.u32.u64 %0, t; }" : "=r"(a) : "l"(p));
    return a;
}
__device__ __forceinline__ void cp16(uint32_t dst, const void* src) {
    asm volatile("cp.async.cg.shared.global [%0], [%1], 16;" :: "r"(dst), "l"(src));
}
#define CP_COMMIT() asm volatile("cp.async.commit_group;" ::: "memory")
#define CP_WAIT(n)  asm volatile("cp.async.wait_group %0;" :: "n"(n) : "memory")

__device__ __forceinline__ void ldsm_x4(uint32_t addr, uint32_t* r) {
    asm volatile("ldmatrix.sync.aligned.m8n8.x4.shared.b16 {%0,%1,%2,%3}, [%4];"
        : "=r"(r[0]), "=r"(r[1]), "=r"(r[2]), "=r"(r[3]) : "r"(addr));
}
__device__ __forceinline__ void ldsm_x2t(uint32_t addr, uint32_t* r) {
    asm volatile("ldmatrix.sync.aligned.m8n8.x2.trans.shared.b16 {%0,%1}, [%2];"
        : "=r"(r[0]), "=r"(r[1]) : "r"(addr));
}
__device__ __forceinline__ void mma_f16(float* c, const uint32_t* a, const uint32_t* b) {
    asm volatile("mma.sync.aligned.m16n8k16.row.col.f32.f16.f16.f32 "
        "{%0,%1,%2,%3}, {%4,%5,%6,%7}, {%8,%9}, {%0,%1,%2,%3};"
        : "+f"(c[0]), "+f"(c[1]), "+f"(c[2]), "+f"(c[3])
        : "r"(a[0]), "r"(a[1]), "r"(a[2]), "r"(a[3]), "r"(b[0]), "r"(b[1]));
}

// ---- packed f32x2 helpers (sm_100+ base ISA) ----
typedef unsigned long long u64;
__device__ __forceinline__ u64 f2b(float x) {
    u64 r; asm("mov.b64 %0, {%1, %1};" : "=l"(r) : "f"(x)); return r;
}
__device__ __forceinline__ float f2hadd(u64 v) {
    float a, b; asm("mov.b64 {%0, %1}, %2;" : "=f"(a), "=f"(b) : "l"(v)); return a + b;
}
__device__ __forceinline__ u64 f2fma(u64 a, u64 b, u64 c) {
    u64 d; asm("fma.rn.f32x2 %0, %1, %2, %3;" : "=l"(d) : "l"(a), "l"(b), "l"(c)); return d;
}
__device__ __forceinline__ u64 f2mul(u64 a, u64 b) {
    u64 d; asm("mul.rn.f32x2 %0, %1, %2;" : "=l"(d) : "l"(a), "l"(b)); return d;
}

// =====================================================================
// fp16 mma.sync GEMM (unchanged, proven).
// =====================================================================
static constexpr uint32_t STAGE = 49152;
static constexpr uint32_t GEMM_SMEM = 4 * STAGE;   // 192KB

__global__ __launch_bounds__(512, 1) void mma_gemm(
    const __half* __restrict__ A, const __half* __restrict__ B, float* __restrict__ C,
    int K, int ldb, int ldc)
{
    extern __shared__ char smem[];
    const uint32_t sbase = smem_u32(smem);
    const int tid  = threadIdx.x;
    const int lane = tid & 31;
    const int w    = tid >> 5;
    const int wm   = w >> 2;
    const int wn   = w & 3;
    const int c4   = lane & 3;
    const int g    = lane >> 2;
    const int row0 = blockIdx.x * 256;
    const int col0 = blockIdx.y * 128;
    const int mA   = lane >> 3;
    const int iA   = lane & 7;

    float acc[4][4][4];
#pragma unroll
    for (int mi = 0; mi < 4; mi++)
#pragma unroll
        for (int ni = 0; ni < 4; ni++)
#pragma unroll
            for (int q = 0; q < 4; q++) acc[mi][ni][q] = 0.f;

    const int nt = K >> 6;

    auto issue = [&](int t, int st) {
        const int k0 = t << 6;
        const uint32_t sA = sbase + st * STAGE;
        const uint32_t sB = sA + 32768;
#pragma unroll
        for (int it = 0; it < 4; it++) {
            int idx = it * 512 + tid;
            int r = idx >> 3, f = idx & 7;
            cp16(sA + r * 128 + (((uint32_t)(f ^ (r & 7))) << 4),
                 A + (size_t)(row0 + r) * K + k0 + f * 8);
        }
#pragma unroll
        for (int it = 0; it < 2; it++) {
            int idx = it * 512 + tid;
            int k = idx >> 4, cn = idx & 15;
            cp16(sB + k * 256 + (((uint32_t)(cn ^ (k & 7))) << 4),
                 B + (size_t)(k0 + k) * ldb + col0 + cn * 8);
        }
    };

    auto compute = [&](int st) {
        const uint32_t sA = sbase + st * STAGE;
        const uint32_t sB = sA + 32768;
#pragma unroll
        for (int s = 0; s < 4; s++) {
            uint32_t af[4][4];
            uint32_t bf[4][2];
#pragma unroll
            for (int mi = 0; mi < 4; mi++) {
                int row = wm * 64 + mi * 16 + iA + ((mA & 1) << 3);
                int f = 2 * s + (mA >> 1);
                ldsm_x4(sA + row * 128 + (((uint32_t)(f ^ (row & 7))) << 4), af[mi]);
            }
#pragma unroll
            for (int ni = 0; ni < 4; ni++) {
                int cn = 4 * wn + ni;
                int k = 16 * s + ((mA & 1) << 3) + iA;
                ldsm_x2t(sB + k * 256 + (((uint32_t)(cn ^ (k & 7))) << 4), bf[ni]);
            }
#pragma unroll
            for (int mi = 0; mi < 4; mi++)
#pragma unroll
                for (int ni = 0; ni < 4; ni++)
                    mma_f16(acc[mi][ni], af[mi], bf[ni]);
        }
    };

    issue(0, 0); CP_COMMIT();
    issue(1, 1); CP_COMMIT();
    issue(2, 2); CP_COMMIT();
    int st = 0;
    for (int t = 0; t < nt; t++) {
        if (t + 3 < nt) {
            CP_WAIT(2);
            __syncthreads();
            issue(t + 3, (st + 3) & 3);
            CP_COMMIT();
        } else {
            CP_WAIT(0);
            __syncthreads();
        }
        compute(st);
        st = (st + 1) & 3;
    }

#pragma unroll
    for (int mi = 0; mi < 4; mi++) {
        const int r0 = row0 + wm * 64 + mi * 16 + g;
#pragma unroll
        for (int ni = 0; ni < 4; ni++) {
            const int cc = col0 + wn * 32 + ni * 8 + 2 * c4;
            *(float2*)(C + (size_t)r0 * ldc + cc) =
                make_float2(acc[mi][ni][0], acc[mi][ni][1]);
            *(float2*)(C + (size_t)(r0 + 8) * ldc + cc) =
                make_float2(acc[mi][ni][2], acc[mi][ni][3]);
        }
    }
}

// ================= weight pack (fp16) =================
__global__ void pack_w(const float* __restrict__ Wq, const float* __restrict__ Wk,
                       const float* __restrict__ Wv, const float* __restrict__ Wg,
                       const float* __restrict__ Wa, const float* __restrict__ Wb,
                       __half* __restrict__ P)
{
    int idx = blockIdx.x * 256 + threadIdx.x;
    int k = idx / 3136;
    int n = (idx - k * 3136) * 4;
    float4 v = make_float4(0.f, 0.f, 0.f, 0.f);
    if      (n < OFF_K)   v = *(const float4*)(Wq + (size_t)k * 2048 + n);
    else if (n < OFF_V)   v = *(const float4*)(Wk + (size_t)k * 2048 + n - OFF_K);
    else if (n < OFF_G)   v = *(const float4*)(Wv + (size_t)k * 4096 + n - OFF_V);
    else if (n < OFF_A)   v = *(const float4*)(Wg + (size_t)k * 4096 + n - OFF_G);
    else if (n < OFF_B2)  v = *(const float4*)(Wa + (size_t)k * 32 + n - OFF_A);
    else if (n < OFF_END) v = *(const float4*)(Wb + (size_t)k * 32 + n - OFF_B2);
    __half* p = P + (size_t)k * NPACK + n;
    *(__half2*)(p + 0) = __floats2half2_rn(v.x, v.y);
    *(__half2*)(p + 2) = __floats2half2_rn(v.z, v.w);
}

// float -> fp16 copy
__global__ void half_copy(const float* __restrict__ src, __half* __restrict__ dst)
{
    int i = (blockIdx.x * 256 + threadIdx.x) * 4;
    float4 v = *(const float4*)(src + i);
    *(__half2*)(dst + i + 0) = __floats2half2_rn(v.x, v.y);
    *(__half2*)(dst + i + 2) = __floats2half2_rn(v.z, v.w);
}

// =====================================================================
// Fused: v-conv+SiLU; q/k conv+SiLU+l2norm+permute; gate/beta.
// Fast-math sigmoid/silu (__expf + __fdividef).
// =====================================================================
__global__ void conv_norm(const float* __restrict__ big,
                          const float* __restrict__ cq, const float* __restrict__ ck,
                          const float* __restrict__ cv, const float* __restrict__ dtb,
                          const float* __restrict__ Alg, float* __restrict__ acts,
                          float* __restrict__ egT, float* __restrict__ btT,
                          float* __restrict__ qn, float* __restrict__ kn)
{
    int b = blockIdx.x;
    float4 z = make_float4(0.f, 0.f, 0.f, 0.f);
    if (b < 8192) {
        int gid = b * 256 + threadIdx.x;
        int t = gid >> 10;
        int c = (gid & 1023) << 2;
        const float* wp = cv + c * 4;
        float4 w0 = *(const float4*)(wp + 0), w1 = *(const float4*)(wp + 4);
        float4 w2 = *(const float4*)(wp + 8), w3 = *(const float4*)(wp + 12);
        const float* xp = big + (size_t)t * NPACK + 4096 + c;
        float4 x3 = *(const float4*)xp;
        float4 x2 = (t >= 1) ? *(const float4*)(xp - NPACK)     : z;
        float4 x1 = (t >= 2) ? *(const float4*)(xp - 2 * NPACK) : z;
        float4 x0 = (t >= 3) ? *(const float4*)(xp - 3 * NPACK) : z;
        float4 o;
        o.x = w0.x * x0.x + w0.y * x1.x + w0.z * x2.x + w0.w * x3.x;
        o.y = w1.x * x0.y + w1.y * x1.y + w1.z * x2.y + w1.w * x3.y;
        o.z = w2.x * x0.z + w2.y * x1.z + w2.z * x2.z + w2.w * x3.z;
        o.w = w3.x * x0.w + w3.y * x1.w + w3.z * x2.w + w3.w * x3.w;
        o.x = fsilu(o.x); o.y = fsilu(o.y); o.z = fsilu(o.z); o.w = fsilu(o.w);
        *(float4*)(acts + (size_t)t * 8192 + 4096 + c) = o;
    } else if (b < 16384) {
        int gw   = (b - 8192) * 8 + (threadIdx.x >> 5);
        int lane = threadIdx.x & 31;
        int t     = gw >> 5;
        int rest  = gw & 31;
        int which = rest & 1;
        int hh    = rest >> 1;
        int cl    = lane * 4;
        const float* wp = (which ? ck : cq) + (hh * 128 + cl) * 4;
        float4 w0 = *(const float4*)(wp + 0), w1 = *(const float4*)(wp + 4);
        float4 w2 = *(const float4*)(wp + 8), w3 = *(const float4*)(wp + 12);
        const float* xp = big + (size_t)t * NPACK + which * 2048 + hh * 128 + cl;
        float4 x3 = *(const float4*)xp;
        float4 x2 = (t >= 1) ? *(const float4*)(xp - NPACK)     : z;
        float4 x1 = (t >= 2) ? *(const float4*)(xp - 2 * NPACK) : z;
        float4 x0 = (t >= 3) ? *(const float4*)(xp - 3 * NPACK) : z;
        float v[4];
        v[0] = w0.x * x0.x + w0.y * x1.x + w0.z * x2.x + w0.w * x3.x;
        v[1] = w1.x * x0.y + w1.y * x1.y + w1.z * x2.y + w1.w * x3.y;
        v[2] = w2.x * x0.z + w2.y * x1.z + w2.z * x2.z + w2.w * x3.z;
        v[3] = w3.x * x0.w + w3.y * x1.w + w3.z * x2.w + w3.w * x3.w;
#pragma unroll
        for (int j = 0; j < 4; j++) v[j] = fsilu(v[j]);
        float ss = v[0] * v[0] + v[1] * v[1] + v[2] * v[2] + v[3] * v[3];
#pragma unroll
        for (int off = 16; off; off >>= 1) ss += __shfl_xor_sync(0xffffffffu, ss, off);
        float s = rsqrtf(ss + 1e-6f);
        if (which == 0) s *= 0.08838834764831845f;
        float* dst = (which ? kn : qn) + (size_t)t * 2048 + hh * 128;
#pragma unroll
        for (int j = 0; j < 4; j++) {
            int c = cl + j;
            dst[((c & 15) << 3) + (c >> 4)] = v[j] * s;
        }
    } else {
        int i = (b - 16384) * 256 + threadIdx.x;
        int t = i >> 5, hh = i & 31;
        float x  = big[(size_t)t * NPACK + OFF_A + hh] + dtb[hh];
        float sp = (x <= 20.f) ? __logf(1.f + __expf(x)) : x;
        egT[(size_t)hh * T_ + t] = __expf(-expf(Alg[hh]) * sp);
        float xb = big[(size_t)t * NPACK + OFF_B2 + hh];
        btT[(size_t)hh * T_ + t] = fsigm(xb);
    }
}

// =====================================================================
// one warp per (pair p, hk): 4 dot families for the lookahead scan.
// =====================================================================
__global__ void qk_dot3(const float* __restrict__ qn, const float* __restrict__ kn,
                        float* __restrict__ qkd, float* __restrict__ kkx,
                        float* __restrict__ qkx)
{
    int wid  = (blockIdx.x * 256 + threadIdx.x) >> 5;   // 0..16383
    int lane = threadIdx.x & 31;
    int p = wid >> 4, hk = wid & 15;
    int t = p << 1;
    const float* qs = qn + (size_t)t * 2048 + hk * 128 + lane * 4;
    const float* ks = kn + (size_t)t * 2048 + hk * 128 + lane * 4;
    float4 q0 = *(const float4*)qs;
    float4 k0 = *(const float4*)ks;
    float4 q1 = *(const float4*)(qs + 2048);
    float4 k1 = *(const float4*)(ks + 2048);
    float r0 = q0.x * k0.x + q0.y * k0.y + q0.z * k0.z + q0.w * k0.w;
    float r1 = q1.x * k1.x + q1.y * k1.y + q1.z * k1.z + q1.w * k1.w;
    float r2 = k1.x * k0.x + k1.y * k0.y + k1.z * k0.z + k1.w * k0.w;
    float r3 = q1.x * k0.x + q1.y * k0.y + q1.z * k0.z + q1.w * k0.w;
#pragma unroll
    for (int off = 16; off; off >>= 1) {
        r0 += __shfl_xor_sync(0xffffffffu, r0, off);
        r1 += __shfl_xor_sync(0xffffffffu, r1, off);
        r2 += __shfl_xor_sync(0xffffffffu, r2, off);
        r3 += __shfl_xor_sync(0xffffffffu, r3, off);
    }
    if (lane == 0) {
        qkd[(size_t)hk * T_ + t]     = r0;
        qkd[(size_t)hk * T_ + t + 1] = r1;
        kkx[(size_t)hk * 1024 + p]   = r2;
        qkx[(size_t)hk * 1024 + p]   = r3;
    }
}

// =====================================================================
// Gated delta-rule scan v4 (2-step lookahead); unroll 2 on the pair
// loop so next-pair smem loads hoist above the current butterfly.
// =====================================================================
__global__ __launch_bounds__(128) void gdn_scan(
    const float* __restrict__ qp, const float* __restrict__ kp,
    const float* __restrict__ acts, const float* __restrict__ egT,
    const float* __restrict__ btT, const float* __restrict__ qkd,
    const float* __restrict__ kkx, const float* __restrict__ qkx,
    float* __restrict__ o)
{
    const int h    = blockIdx.y;
    const int dvt  = blockIdx.x;
    const int hk   = h >> 1;
    const int tid  = threadIdx.x;
    const int w    = tid >> 5;
    const int lane = tid & 31;
    const int dkg  = lane >> 1;
    const int dvg  = lane & 1;

    __shared__ float sq[2][32][128];
    __shared__ float sk[2][32][128];
    __shared__ float sv[2][32][16];
    __shared__ float se[2][32];
    __shared__ float sb[2][32];
    __shared__ float sqk[2][32];
    __shared__ float skk[2][16];
    __shared__ float sqx[2][16];

    auto fill = [&](int buf, int t0) {
#pragma unroll
        for (int it = 0; it < 8; it++) {
            int idx = it * 128 + tid;
            int tt = idx >> 5, f = (idx & 31) << 2;
            cp16(smem_u32(&sq[buf][tt][f]), qp + (size_t)(t0 + tt) * 2048 + hk * 128 + f);
            cp16(smem_u32(&sk[buf][tt][f]), kp + (size_t)(t0 + tt) * 2048 + hk * 128 + f);
        }
        {
            int tt = tid >> 2, f = (tid & 3) << 2;
            cp16(smem_u32(&sv[buf][tt][f]),
                 acts + (size_t)(t0 + tt) * 8192 + 4096 + h * 128 + dvt * 16 + f);
        }
        if (tid < 8)
            cp16(smem_u32(&se[buf][tid << 2]), egT + (size_t)h * T_ + t0 + (tid << 2));
        else if (tid < 16)
            cp16(smem_u32(&sb[buf][(tid - 8) << 2]), btT + (size_t)h * T_ + t0 + ((tid - 8) << 2));
        else if (tid < 24)
            cp16(smem_u32(&sqk[buf][(tid - 16) << 2]), qkd + (size_t)hk * T_ + t0 + ((tid - 16) << 2));
        else if (tid < 28)
            cp16(smem_u32(&skk[buf][(tid - 24) << 2]), kkx + (size_t)hk * 1024 + (t0 >> 1) + ((tid - 24) << 2));
        else if (tid < 32)
            cp16(smem_u32(&sqx[buf][(tid - 28) << 2]), qkx + (size_t)hk * 1024 + (t0 >> 1) + ((tid - 28) << 2));
    };

    u64 S2[4][2];
#pragma unroll
    for (int i = 0; i < 4; i++) { S2[i][0] = 0ull; S2[i][1] = 0ull; }

    fill(0, 0); CP_COMMIT();

    for (int c = 0; c < 64; c++) {
        const int buf = c & 1;
        if (c + 1 < 64) { fill(buf ^ 1, (c + 1) << 5); CP_COMMIT(); CP_WAIT(1); }
        else            { CP_WAIT(0); }
        __syncthreads();
#pragma unroll 2
        for (int pp = 0; pp < 16; pp++) {
            const int tt = pp << 1;
            ulonglong2 a0, a1;
            a0 = *(const ulonglong2*)&sk[buf][tt][dkg << 3];
            a1 = *(const ulonglong2*)&sk[buf][tt][(dkg << 3) + 4];
            u64 kt[4]  = {a0.x, a0.y, a1.x, a1.y};
            a0 = *(const ulonglong2*)&sq[buf][tt][dkg << 3];
            a1 = *(const ulonglong2*)&sq[buf][tt][(dkg << 3) + 4];
            u64 qt[4]  = {a0.x, a0.y, a1.x, a1.y};
            a0 = *(const ulonglong2*)&sk[buf][tt + 1][dkg << 3];
            a1 = *(const ulonglong2*)&sk[buf][tt + 1][(dkg << 3) + 4];
            u64 kt1[4] = {a0.x, a0.y, a1.x, a1.y};
            a0 = *(const ulonglong2*)&sq[buf][tt + 1][dkg << 3];
            a1 = *(const ulonglong2*)&sq[buf][tt + 1][(dkg << 3) + 4];
            u64 qt1[4] = {a0.x, a0.y, a1.x, a1.y};
            float2 v0 = *(const float2*)&sv[buf][tt][(w << 2) + (dvg << 1)];
            float2 v1 = *(const float2*)&sv[buf][tt + 1][(w << 2) + (dvg << 1)];
            float e0 = se[buf][tt], e1 = se[buf][tt + 1];
            float b0 = sb[buf][tt], b1 = sb[buf][tt + 1];
            float qk0 = sqk[buf][tt], qk1 = sqk[buf][tt + 1];
            float kk = skk[buf][pp], qx = sqx[buf][pp];

            u64 kv1a = 0ull, kv1b = 0ull, kv2a = 0ull, kv2b = 0ull;
            u64 oq1a = 0ull, oq1b = 0ull, oq2a = 0ull, oq2b = 0ull;
#pragma unroll
            for (int i = 0; i < 4; i++) {
                kv1a = f2fma(kt[i],  S2[i][0], kv1a);
                kv1b = f2fma(kt[i],  S2[i][1], kv1b);
                kv2a = f2fma(kt1[i], S2[i][0], kv2a);
                kv2b = f2fma(kt1[i], S2[i][1], kv2b);
                oq1a = f2fma(qt[i],  S2[i][0], oq1a);
                oq1b = f2fma(qt[i],  S2[i][1], oq1b);
                oq2a = f2fma(qt1[i], S2[i][0], oq2a);
                oq2b = f2fma(qt1[i], S2[i][1], oq2b);
            }
            float r[8] = {f2hadd(kv1a), f2hadd(kv1b), f2hadd(kv2a), f2hadd(kv2b),
                          f2hadd(oq1a), f2hadd(oq1b), f2hadd(oq2a), f2hadd(oq2b)};
#pragma unroll
            for (int m = 2; m <= 16; m <<= 1) {
#pragma unroll
                for (int j = 0; j < 8; j++)
                    r[j] += __shfl_xor_sync(0xffffffffu, r[j], m);
            }
            float d0 = b0 * (v0.x - e0 * r[0]);
            float d1 = b0 * (v0.y - e0 * r[1]);
            float dn0 = b1 * (v1.x - e1 * fmaf(kk, d0, e0 * r[2]));
            float dn1 = b1 * (v1.y - e1 * fmaf(kk, d1, e0 * r[3]));

            float ee = e0 * e1, ed0 = e1 * d0, ed1 = e1 * d1;
            u64 ee2 = f2b(ee), ed02 = f2b(ed0), ed12 = f2b(ed1);
            u64 dn02 = f2b(dn0), dn12 = f2b(dn1);
#pragma unroll
            for (int i = 0; i < 4; i++) {
                S2[i][0] = f2fma(S2[i][0], ee2, f2fma(kt1[i], dn02, f2mul(kt[i], ed02)));
                S2[i][1] = f2fma(S2[i][1], ee2, f2fma(kt1[i], dn12, f2mul(kt[i], ed12)));
            }
            if (dkg == 0) {
                float2 o0 = make_float2(fmaf(qk0, d0, e0 * r[4]),
                                        fmaf(qk0, d1, e0 * r[5]));
                float2 o1 = make_float2(fmaf(qk1, dn0, e1 * fmaf(qx, d0, e0 * r[6])),
                                        fmaf(qk1, dn1, e1 * fmaf(qx, d1, e0 * r[7])));
                size_t ob = (size_t)((c << 5) + tt) * 4096 + h * 128
                          + dvt * 16 + (w << 2) + (dvg << 1);
                *(float2*)(o + ob) = o0;
                *(float2*)(o + ob + 4096) = o1;
            }
        }
        __syncthreads();
    }
}

// ============ gated RMSNorm + silu(gate), fp16 output ============
__global__ void gate_norm(const float* __restrict__ o, const float* __restrict__ big,
                          const float* __restrict__ wn, __half* __restrict__ og)
{
    int wid  = (blockIdx.x * blockDim.x + threadIdx.x) >> 5;
    int lane = threadIdx.x & 31;
    int t = wid >> 5;
    int h = wid & 31;
    size_t base = (size_t)t * 4096 + h * 128 + lane * 4;
    float4 x = *(const float4*)(o + base);
    float ss = x.x * x.x + x.y * x.y + x.z * x.z + x.w * x.w;
#pragma unroll
    for (int off = 16; off; off >>= 1) ss += __shfl_xor_sync(0xffffffffu, ss, off);
    float r = rsqrtf(ss * (1.f / 128.f) + 1e-5f);
    float4 gv = *(const float4*)(big + (size_t)t * NPACK + OFF_G + h * 128 + lane * 4);
    float4 wv = *(const float4*)(wn + lane * 4);
    float ox = x.x * r * wv.x * fsilu(gv.x);
    float oy = x.y * r * wv.y * fsilu(gv.y);
    float oz = x.z * r * wv.z * fsilu(gv.z);
    float ow = x.w * r * wv.w * fsilu(gv.w);
    *(__half2*)(og + base + 0) = __floats2half2_rn(ox, oy);
    *(__half2*)(og + base + 2) = __floats2half2_rn(oz, ow);
}

// =====================================================================
extern "C" void kernel_launch(void* const* d_in, const int* in_sizes, int n_in,
                              void* d_out, int out_size)
{
    const float* h   = (const float*)d_in[0];
    const float* Wq  = (const float*)d_in[1];
    const float* Wk  = (const float*)d_in[2];
    const float* Wv  = (const float*)d_in[3];
    const float* Wa  = (const float*)d_in[4];
    const float* Wb  = (const float*)d_in[5];
    const float* Wg  = (const float*)d_in[6];
    const float* cq  = (const float*)d_in[7];
    const float* ck  = (const float*)d_in[8];
    const float* cv  = (const float*)d_in[9];
    const float* dtb = (const float*)d_in[10];
    const float* Alg = (const float*)d_in[11];
    const float* onw = (const float*)d_in[12];
    const float* Wo  = (const float*)d_in[13];
    float* out = (float*)d_out;

    float *big, *acts, *egT, *btT, *qn, *kn, *qkd, *kkx, *qkx, *o;
    __half *Wp, *hr, *WoR, *og;
    cudaGetSymbolAddress((void**)&big,  g_big);
    cudaGetSymbolAddress((void**)&Wp,   g_Wp);
    cudaGetSymbolAddress((void**)&hr,   g_hr);
    cudaGetSymbolAddress((void**)&WoR,  g_WoR);
    cudaGetSymbolAddress((void**)&acts, g_acts);
    cudaGetSymbolAddress((void**)&egT,  g_egT);
    cudaGetSymbolAddress((void**)&btT,  g_btT);
    cudaGetSymbolAddress((void**)&qn,   g_qn);
    cudaGetSymbolAddress((void**)&kn,   g_kn);
    cudaGetSymbolAddress((void**)&qkd,  g_qkd);
    cudaGetSymbolAddress((void**)&kkx,  g_kkx);
    cudaGetSymbolAddress((void**)&qkx,  g_qkx);
    cudaGetSymbolAddress((void**)&o,    g_o);
    cudaGetSymbolAddress((void**)&og,   g_og);

    cudaFuncSetAttribute(mma_gemm, cudaFuncAttributeMaxDynamicSharedMemorySize, GEMM_SMEM);

    // launches 1-3: preprocessing (GEMM is 4th so ncu -s5 captures it)
    half_copy<<<(2048 * 2048 / 4) / 256, 256>>>(h, hr);
    pack_w<<<2048 * 3136 / 256, 256>>>(Wq, Wk, Wv, Wg, Wa, Wb, Wp);
    half_copy<<<(4096 * 2048 / 4) / 256, 256>>>(Wo, WoR);

    // 4: fused projection GEMM
    mma_gemm<<<dim3(8, 98), 512, GEMM_SMEM>>>(hr, Wp, big, 2048, NPACK, NPACK);

    conv_norm<<<16640, 256>>>(big, cq, ck, cv, dtb, Alg, acts, egT, btT, qn, kn);
    qk_dot3<<<2048, 256>>>(qn, kn, qkd, kkx, qkx);
    gdn_scan<<<dim3(8, 32), 128>>>(qn, kn, acts, egT, btT, qkd, kkx, qkx, o);
    gate_norm<<<8192, 256>>>(o, big, onw, og);

    mma_gemm<<<dim3(8, 16), 512, GEMM_SMEM>>>(og, WoR, out, 4096, 2048, 2048);
}